// round 13
// baseline (speedup 1.0000x reference)
#include <cuda_runtime.h>
#include <cuda_bf16.h>
#include <cstdint>

// ---------------- problem constants ----------------
#define B_   8
#define C_   512
#define NPIX 4096          // H*W = 64*64
#define CK   256
#define CV   256
#define CO   512
#define EPS  1e-5f

// ---------------- scratch (device globals; no allocation allowed) ----------
__device__ float g_qk [B_ * CK * NPIX];   // conv-k output, pre-BN   [B,Ck,N]
__device__ float g_vT [B_ * NPIX * CV];   // value transposed        [B,N,Cv]
__device__ float g_ctx[B_ * NPIX * CV];   // attention output        [B,N,Cv]
__device__ float g_mean[CK];
__device__ float g_rstd[CK];

// =====================================================================
// Kernel 1: fused QKV 1x1 conv GEMM.
//   For each batch b:  Y[o, n] = sum_c W[o,c] * x[b,c,n] + bias[o]
//   o in [0,256) -> qk scratch (Wk), o in [256,512) -> value (Wv) in d_out.
//   Tiles: BM=128 (o), BN=128 (n), BK=16; 256 thr, 8x8 micro-tile.
// =====================================================================
#define G_BM 128
#define G_BN 128
#define G_BK 16
#define A_LD 132

__global__ void __launch_bounds__(256) gemm_qkv_kernel(
    const float* __restrict__ x,
    const float* __restrict__ Wk, const float* __restrict__ bk,
    const float* __restrict__ Wv, const float* __restrict__ bv,
    float* __restrict__ value)
{
    __shared__ float As[G_BK][A_LD];
    __shared__ float Bs[G_BK][G_BN];

    const int b  = blockIdx.z;
    const int o0 = blockIdx.y * G_BM;
    const int n0 = blockIdx.x * G_BN;
    const int tid = threadIdx.x;
    const int tx = tid & 15, ty = tid >> 4;

    const bool is_k = (o0 < CK);
    const float* W    = is_k ? Wk : Wv;
    const float* bias = is_k ? bk : bv;
    float*       dst  = is_k ? g_qk : value;
    const int or0 = o0 & (CK - 1);

    float acc[8][8];
    #pragma unroll
    for (int i = 0; i < 8; i++)
        #pragma unroll
        for (int j = 0; j < 8; j++) acc[i][j] = 0.f;

    for (int c0 = 0; c0 < C_; c0 += G_BK) {
        // A tile: W rows (k contiguous in gmem) -> transposed into As[k][m]
        #pragma unroll
        for (int r = 0; r < 2; r++) {
            int idx = tid + r * 256;          // 0..511 float4 slots
            int m  = idx >> 2;
            int kq = idx & 3;
            float4 v = *(const float4*)(W + (size_t)(or0 + m) * C_ + c0 + kq * 4);
            As[kq*4+0][m] = v.x; As[kq*4+1][m] = v.y;
            As[kq*4+2][m] = v.z; As[kq*4+3][m] = v.w;
        }
        // B tile: x[b, c0+k, n0+n] contiguous in n -> direct
        #pragma unroll
        for (int r = 0; r < 2; r++) {
            int idx = tid + r * 256;
            int k  = idx >> 5;
            int nq = idx & 31;
            *(float4*)&Bs[k][nq*4] =
                *(const float4*)(x + (((size_t)b * C_ + c0 + k) << 12) + n0 + nq * 4);
        }
        __syncthreads();
        #pragma unroll
        for (int k = 0; k < G_BK; k++) {
            float a[8], bb[8];
            *(float4*)&a[0]  = *(float4*)&As[k][ty*8];
            *(float4*)&a[4]  = *(float4*)&As[k][ty*8+4];
            *(float4*)&bb[0] = *(float4*)&Bs[k][tx*8];
            *(float4*)&bb[4] = *(float4*)&Bs[k][tx*8+4];
            #pragma unroll
            for (int i = 0; i < 8; i++)
                #pragma unroll
                for (int j = 0; j < 8; j++)
                    acc[i][j] += a[i] * bb[j];
        }
        __syncthreads();
    }

    #pragma unroll
    for (int i = 0; i < 8; i++) {
        int o = or0 + ty * 8 + i;
        float bi = bias[o];
        float* p = dst + (((size_t)b * CK + o) << 12) + n0 + tx * 8;
        float4 v0 = {acc[i][0]+bi, acc[i][1]+bi, acc[i][2]+bi, acc[i][3]+bi};
        float4 v1 = {acc[i][4]+bi, acc[i][5]+bi, acc[i][6]+bi, acc[i][7]+bi};
        *(float4*)p       = v0;
        *(float4*)(p + 4) = v1;
    }
}

// =====================================================================
// Kernel 2: BN training statistics per channel over (B, N) = 32768 vals.
// =====================================================================
__global__ void __launch_bounds__(256) bn_stats_kernel()
{
    const int ck = blockIdx.x;
    float s = 0.f, s2 = 0.f;
    for (int i = threadIdx.x; i < B_ * NPIX; i += 256) {
        int b = i >> 12;
        int n = i & (NPIX - 1);
        float v = g_qk[(((size_t)b * CK + ck) << 12) + n];
        s += v; s2 += v * v;
    }
    #pragma unroll
    for (int off = 16; off > 0; off >>= 1) {
        s  += __shfl_xor_sync(0xffffffffu, s,  off);
        s2 += __shfl_xor_sync(0xffffffffu, s2, off);
    }
    __shared__ float sb[16];
    int w = threadIdx.x >> 5;
    if ((threadIdx.x & 31) == 0) { sb[w] = s; sb[8 + w] = s2; }
    __syncthreads();
    if (threadIdx.x == 0) {
        float S = 0.f, S2 = 0.f;
        #pragma unroll
        for (int i = 0; i < 8; i++) { S += sb[i]; S2 += sb[8 + i]; }
        const float invN = 1.f / (float)(B_ * NPIX);
        float mean = S * invN;
        float var  = S2 * invN - mean * mean;
        g_mean[ck] = mean;
        g_rstd[ck] = rsqrtf(var + EPS);
    }
}

// =====================================================================
// Kernel 3: feat = relu((qk-mean)*rstd*gamma + beta) -> two d_out slots
// =====================================================================
__global__ void __launch_bounds__(256) feat_kernel(
    const float* __restrict__ gamma, const float* __restrict__ beta,
    float* __restrict__ feat1, float* __restrict__ feat2)
{
    int i4 = blockIdx.x * 256 + threadIdx.x;     // float4 index
    int e  = i4 * 4;
    int ck = (e >> 12) & (CK - 1);
    float mu = g_mean[ck], r = g_rstd[ck];
    float sc = r * gamma[ck], be = beta[ck];
    float4 v = *(const float4*)(g_qk + e);
    float4 f;
    f.x = fmaxf(0.f, (v.x - mu) * sc + be);
    f.y = fmaxf(0.f, (v.y - mu) * sc + be);
    f.z = fmaxf(0.f, (v.z - mu) * sc + be);
    f.w = fmaxf(0.f, (v.w - mu) * sc + be);
    *(float4*)(feat1 + e) = f;
    *(float4*)(feat2 + e) = f;
}

// =====================================================================
// Kernel 4: value [B,Cv,N] -> vT [B,N,Cv]  (32x32 smem transpose)
// =====================================================================
__global__ void __launch_bounds__(256) transpose_v_kernel(const float* __restrict__ value)
{
    __shared__ float t[32][33];
    const int b  = blockIdx.z;
    const int n0 = blockIdx.x * 32;
    const int c0 = blockIdx.y * 32;
    #pragma unroll
    for (int r = 0; r < 4; r++) {
        int row = c0 + threadIdx.y + r * 8;
        t[threadIdx.y + r*8][threadIdx.x] =
            value[(((size_t)b * CV + row) << 12) + n0 + threadIdx.x];
    }
    __syncthreads();
    #pragma unroll
    for (int r = 0; r < 4; r++) {
        int row = n0 + threadIdx.y + r * 8;
        g_vT[((size_t)b * NPIX + row) * CV + c0 + threadIdx.x] =
            t[threadIdx.x][threadIdx.y + r*8];
    }
}

// =====================================================================
// Kernel 5: flash attention, fp32.
//   q[m,ck]=feat[b,ck,q0+m], k[n,ck]=feat[b,ck,k0+n], v from g_vT.
//   BM=BN=64, D=256. 256 threads (16x16); each thread: 4x4 of S,
//   4 rows x 16 cols of O. Online softmax via 16-lane shfl reductions.
// =====================================================================
#define PS_LD 65
#define ATTN_SMEM ((16384*3 + 64*PS_LD) * 4)

__global__ void __launch_bounds__(256, 1) attn_kernel(
    const float* __restrict__ feat,   // [B,Ck,N] (d_out feat1 slot)
    float* __restrict__ ctx)          // unused (g_ctx global) kept for clarity
{
    extern __shared__ float sm[];
    float* Qs = sm;                 // [256][64]  (ck-major, m contiguous)
    float* Ks = sm + 16384;         // [256][64]
    float* Vs = sm + 32768;         // [64][256]  (n-major, cv contiguous)
    float* Ps = sm + 49152;         // [64][PS_LD] transposed: Ps[n][m]

    const int b  = blockIdx.y;
    const int q0 = blockIdx.x * 64;
    const float* f  = feat + (size_t)b * CK * NPIX;
    const float* vt = g_vT + (size_t)b * NPIX * CV;

    const int tid = threadIdx.x;
    const int tx = tid & 15, ty = tid >> 4;
    const int mb = ty * 4, nb = tx * 4;

    // load Q tile once
    #pragma unroll
    for (int r = 0; r < 16; r++) {
        int idx = tid + r * 256;          // float4 slots, 4096 total
        int ck = idx >> 4, mq = idx & 15;
        *(float4*)&Qs[ck * 64 + mq * 4] =
            *(const float4*)(f + ((size_t)ck << 12) + q0 + mq * 4);
    }

    float M[4], L[4], O[4][16];
    #pragma unroll
    for (int i = 0; i < 4; i++) {
        M[i] = -1e30f; L[i] = 0.f;
        #pragma unroll
        for (int j = 0; j < 16; j++) O[i][j] = 0.f;
    }

    for (int kb = 0; kb < NPIX / 64; kb++) {
        const int k0 = kb * 64;
        __syncthreads();   // prior iter finished reading Ks/Vs/Ps (also orders Q load)
        #pragma unroll
        for (int r = 0; r < 16; r++) {
            int idx = tid + r * 256;
            int ck = idx >> 4, mq = idx & 15;
            *(float4*)&Ks[ck * 64 + mq * 4] =
                *(const float4*)(f + ((size_t)ck << 12) + k0 + mq * 4);
        }
        #pragma unroll
        for (int r = 0; r < 16; r++) {
            int idx = tid + r * 256;
            int n = idx >> 6, cq = idx & 63;
            *(float4*)&Vs[n * 256 + cq * 4] =
                *(const float4*)(vt + (size_t)(k0 + n) * CV + cq * 4);
        }
        __syncthreads();

        // ---- S = Q K^T (4x4 per thread) ----
        float s[4][4];
        #pragma unroll
        for (int i = 0; i < 4; i++)
            #pragma unroll
            for (int j = 0; j < 4; j++) s[i][j] = 0.f;

        #pragma unroll 8
        for (int ck = 0; ck < CK; ck++) {
            float4 a = *(float4*)&Qs[ck * 64 + mb];
            float4 k = *(float4*)&Ks[ck * 64 + nb];
            s[0][0] += a.x*k.x; s[0][1] += a.x*k.y; s[0][2] += a.x*k.z; s[0][3] += a.x*k.w;
            s[1][0] += a.y*k.x; s[1][1] += a.y*k.y; s[1][2] += a.y*k.z; s[1][3] += a.y*k.w;
            s[2][0] += a.z*k.x; s[2][1] += a.z*k.y; s[2][2] += a.z*k.z; s[2][3] += a.z*k.w;
            s[3][0] += a.w*k.x; s[3][1] += a.w*k.y; s[3][2] += a.w*k.z; s[3][3] += a.w*k.w;
        }

        // ---- online softmax ----
        const float scale = 0.0625f;    // 1/sqrt(256)
        float rm[4];
        #pragma unroll
        for (int i = 0; i < 4; i++) {
            s[i][0] *= scale; s[i][1] *= scale; s[i][2] *= scale; s[i][3] *= scale;
            rm[i] = fmaxf(fmaxf(s[i][0], s[i][1]), fmaxf(s[i][2], s[i][3]));
        }
        #pragma unroll
        for (int off = 8; off > 0; off >>= 1)
            #pragma unroll
            for (int i = 0; i < 4; i++)
                rm[i] = fmaxf(rm[i], __shfl_xor_sync(0xffffffffu, rm[i], off));

        float c[4], rs[4];
        #pragma unroll
        for (int i = 0; i < 4; i++) {
            float mn = fmaxf(M[i], rm[i]);
            c[i] = __expf(M[i] - mn);
            M[i] = mn;
            rs[i] = 0.f;
        }
        #pragma unroll
        for (int i = 0; i < 4; i++)
            #pragma unroll
            for (int j = 0; j < 4; j++) {
                float p = __expf(s[i][j] - M[i]);
                Ps[(nb + j) * PS_LD + mb + i] = p;
                rs[i] += p;
            }
        #pragma unroll
        for (int off = 8; off > 0; off >>= 1)
            #pragma unroll
            for (int i = 0; i < 4; i++)
                rs[i] += __shfl_xor_sync(0xffffffffu, rs[i], off);
        #pragma unroll
        for (int i = 0; i < 4; i++) {
            L[i] = L[i] * c[i] + rs[i];
            #pragma unroll
            for (int j = 0; j < 16; j++) O[i][j] *= c[i];
        }
        __syncthreads();

        // ---- O += P V  (k-dim = n, 64 steps) ----
        #pragma unroll 4
        for (int n = 0; n < 64; n++) {
            float p0 = Ps[n * PS_LD + mb + 0];
            float p1 = Ps[n * PS_LD + mb + 1];
            float p2 = Ps[n * PS_LD + mb + 2];
            float p3 = Ps[n * PS_LD + mb + 3];
            #pragma unroll
            for (int j = 0; j < 4; j++) {
                float4 v = *(float4*)&Vs[n * 256 + tx * 4 + j * 64];
                O[0][j*4+0] += p0 * v.x; O[0][j*4+1] += p0 * v.y;
                O[0][j*4+2] += p0 * v.z; O[0][j*4+3] += p0 * v.w;
                O[1][j*4+0] += p1 * v.x; O[1][j*4+1] += p1 * v.y;
                O[1][j*4+2] += p1 * v.z; O[1][j*4+3] += p1 * v.w;
                O[2][j*4+0] += p2 * v.x; O[2][j*4+1] += p2 * v.y;
                O[2][j*4+2] += p2 * v.z; O[2][j*4+3] += p2 * v.w;
                O[3][j*4+0] += p3 * v.x; O[3][j*4+1] += p3 * v.y;
                O[3][j*4+2] += p3 * v.z; O[3][j*4+3] += p3 * v.w;
            }
        }
    }

    // ---- write ctx [B,N,Cv] ----
    #pragma unroll
    for (int i = 0; i < 4; i++) {
        float inv = 1.0f / L[i];
        float* dst = g_ctx + ((size_t)b * NPIX + q0 + mb + i) * CV;
        #pragma unroll
        for (int j = 0; j < 4; j++) {
            float4 o4 = {O[i][j*4+0]*inv, O[i][j*4+1]*inv,
                         O[i][j*4+2]*inv, O[i][j*4+3]*inv};
            *(float4*)(dst + tx * 4 + j * 64) = o4;
        }
    }
}

// =====================================================================
// Kernel 6: out[b,co,n] = sum_cv Ww[co,cv]*ctx[b,n,cv] + bw[co]
//   K = 256, B-tile transposed on load (cv contiguous in gmem).
// =====================================================================
#define B_LD 132
__global__ void __launch_bounds__(256) gemm_out_kernel(
    const float* __restrict__ Ww, const float* __restrict__ bw,
    float* __restrict__ out)
{
    __shared__ float As[G_BK][A_LD];
    __shared__ float Bs[G_BK][B_LD];

    const int b  = blockIdx.z;
    const int o0 = blockIdx.y * G_BM;
    const int n0 = blockIdx.x * G_BN;
    const int tid = threadIdx.x;
    const int tx = tid & 15, ty = tid >> 4;

    float acc[8][8];
    #pragma unroll
    for (int i = 0; i < 8; i++)
        #pragma unroll
        for (int j = 0; j < 8; j++) acc[i][j] = 0.f;

    for (int c0 = 0; c0 < CV; c0 += G_BK) {
        #pragma unroll
        for (int r = 0; r < 2; r++) {
            int idx = tid + r * 256;
            int m  = idx >> 2;
            int kq = idx & 3;
            float4 v = *(const float4*)(Ww + (size_t)(o0 + m) * CV + c0 + kq * 4);
            As[kq*4+0][m] = v.x; As[kq*4+1][m] = v.y;
            As[kq*4+2][m] = v.z; As[kq*4+3][m] = v.w;
        }
        #pragma unroll
        for (int r = 0; r < 2; r++) {
            int idx = tid + r * 256;
            int n  = idx >> 2;
            int kq = idx & 3;
            float4 v = *(const float4*)(g_ctx + ((size_t)b * NPIX + n0 + n) * CV + c0 + kq * 4);
            Bs[kq*4+0][n] = v.x; Bs[kq*4+1][n] = v.y;
            Bs[kq*4+2][n] = v.z; Bs[kq*4+3][n] = v.w;
        }
        __syncthreads();
        #pragma unroll
        for (int k = 0; k < G_BK; k++) {
            float a[8], bb[8];
            *(float4*)&a[0]  = *(float4*)&As[k][ty*8];
            *(float4*)&a[4]  = *(float4*)&As[k][ty*8+4];
            *(float4*)&bb[0] = *(float4*)&Bs[k][tx*8];
            *(float4*)&bb[4] = *(float4*)&Bs[k][tx*8+4];
            #pragma unroll
            for (int i = 0; i < 8; i++)
                #pragma unroll
                for (int j = 0; j < 8; j++)
                    acc[i][j] += a[i] * bb[j];
        }
        __syncthreads();
    }

    #pragma unroll
    for (int i = 0; i < 8; i++) {
        int o = o0 + ty * 8 + i;
        float bi = bw[o];
        float* p = out + (((size_t)b * CO + o) << 12) + n0 + tx * 8;
        float4 v0 = {acc[i][0]+bi, acc[i][1]+bi, acc[i][2]+bi, acc[i][3]+bi};
        float4 v1 = {acc[i][4]+bi, acc[i][5]+bi, acc[i][6]+bi, acc[i][7]+bi};
        *(float4*)p       = v0;
        *(float4*)(p + 4) = v1;
    }
}

// =====================================================================
// launch
// =====================================================================
extern "C" void kernel_launch(void* const* d_in, const int* in_sizes, int n_in,
                              void* d_out, int out_size)
{
    const float* x     = (const float*)d_in[0];
    const float* Wk    = (const float*)d_in[1];
    const float* bk    = (const float*)d_in[2];
    const float* gamma = (const float*)d_in[3];
    const float* beta  = (const float*)d_in[4];
    const float* Wv    = (const float*)d_in[5];
    const float* bv    = (const float*)d_in[6];
    const float* Ww    = (const float*)d_in[7];
    const float* bw    = (const float*)d_in[8];

    float* out   = (float*)d_out;                        // [8,512,64,64]
    float* feat1 = out   + (size_t)B_ * CO * NPIX;       // [8,256,64,64]
    float* feat2 = feat1 + (size_t)B_ * CK * NPIX;       // [8,256,64,64]
    float* value = feat2 + (size_t)B_ * CK * NPIX;       // [8,256,64,64]

    cudaFuncSetAttribute(attn_kernel,
                         cudaFuncAttributeMaxDynamicSharedMemorySize, ATTN_SMEM);

    // 1) fused QK/V conv1x1 GEMM
    gemm_qkv_kernel<<<dim3(NPIX / G_BN, (CK + CV) / G_BM, B_), 256>>>(
        x, Wk, bk, Wv, bv, value);

    // 2) BN stats
    bn_stats_kernel<<<CK, 256>>>();

    // 3) BN normalize + ReLU -> feat (written twice)
    feat_kernel<<<(B_ * CK * NPIX) / (4 * 256), 256>>>(gamma, beta, feat1, feat2);

    // 4) transpose value -> [B,N,Cv]
    transpose_v_kernel<<<dim3(NPIX / 32, CV / 32, B_), dim3(32, 8)>>>(value);

    // 5) flash attention -> g_ctx [B,N,Cv]
    attn_kernel<<<dim3(NPIX / 64, B_), 256, ATTN_SMEM>>>(feat1, nullptr);

    // 6) output conv1x1 GEMM
    gemm_out_kernel<<<dim3(NPIX / G_BN, CO / G_BM, B_), 256>>>(Ww, bw, out);
}

// round 14
// speedup vs baseline: 1.0174x; 1.0174x over previous
#include <cuda_runtime.h>
#include <cuda_bf16.h>
#include <cstdint>

// ---------------- problem constants ----------------
#define B_   8
#define C_   512
#define NPIX 4096          // H*W = 64*64
#define CK   256
#define CV   256
#define CO   512
#define EPS  1e-5f

// ---------------- scratch (device globals; no allocation allowed) ----------
__device__ float g_qk [B_ * CK * NPIX];   // conv-k output, pre-BN   [B,Ck,N]
__device__ float g_vT [B_ * NPIX * CV];   // value transposed        [B,N,Cv]
__device__ float g_ctx[B_ * NPIX * CV];   // attention output        [B,N,Cv]
__device__ float g_mean[CK];
__device__ float g_rstd[CK];

// ---------------- packed f32x2 helpers (FFMA2 path, 2x fp32 rate) ----------
__device__ __forceinline__ unsigned long long f2pack(float lo, float hi) {
    unsigned long long r;
    asm("mov.b64 %0, {%1, %2};" : "=l"(r) : "f"(lo), "f"(hi));
    return r;
}
__device__ __forceinline__ void f2fma(unsigned long long& acc,
                                      unsigned long long a, unsigned long long b) {
    asm("fma.rn.f32x2 %0, %1, %2, %0;" : "+l"(acc) : "l"(a), "l"(b));
}
__device__ __forceinline__ void f2mul(unsigned long long& d, unsigned long long a) {
    asm("mul.rn.f32x2 %0, %0, %1;" : "+l"(d) : "l"(a));
}
__device__ __forceinline__ float2 f2unpack(unsigned long long v) {
    float2 f;
    asm("mov.b64 {%0, %1}, %2;" : "=f"(f.x), "=f"(f.y) : "l"(v));
    return f;
}

// =====================================================================
// Kernel 1: fused QKV 1x1 conv GEMM (f32x2 micro-kernel).
// =====================================================================
#define G_BM 128
#define G_BN 128
#define G_BK 16
#define A_LD 132

__global__ void __launch_bounds__(256) gemm_qkv_kernel(
    const float* __restrict__ x,
    const float* __restrict__ Wk, const float* __restrict__ bk,
    const float* __restrict__ Wv, const float* __restrict__ bv,
    float* __restrict__ value)
{
    __shared__ __align__(16) float As[G_BK][A_LD];
    __shared__ __align__(16) float Bs[G_BK][G_BN];

    const int b  = blockIdx.z;
    const int o0 = blockIdx.y * G_BM;
    const int n0 = blockIdx.x * G_BN;
    const int tid = threadIdx.x;
    const int tx = tid & 15, ty = tid >> 4;

    const bool is_k = (o0 < CK);
    const float* W    = is_k ? Wk : Wv;
    const float* bias = is_k ? bk : bv;
    float*       dst  = is_k ? g_qk : value;
    const int or0 = o0 & (CK - 1);

    unsigned long long acc2[8][4] = {};

    for (int c0 = 0; c0 < C_; c0 += G_BK) {
        #pragma unroll
        for (int r = 0; r < 2; r++) {
            int idx = tid + r * 256;
            int m  = idx >> 2;
            int kq = idx & 3;
            float4 v = *(const float4*)(W + (size_t)(or0 + m) * C_ + c0 + kq * 4);
            As[kq*4+0][m] = v.x; As[kq*4+1][m] = v.y;
            As[kq*4+2][m] = v.z; As[kq*4+3][m] = v.w;
        }
        #pragma unroll
        for (int r = 0; r < 2; r++) {
            int idx = tid + r * 256;
            int k  = idx >> 5;
            int nq = idx & 31;
            *(float4*)&Bs[k][nq*4] =
                *(const float4*)(x + (((size_t)b * C_ + c0 + k) << 12) + n0 + nq * 4);
        }
        __syncthreads();
        #pragma unroll
        for (int k = 0; k < G_BK; k++) {
            float a[8];
            *(float4*)&a[0] = *(float4*)&As[k][ty*8];
            *(float4*)&a[4] = *(float4*)&As[k][ty*8+4];
            ulonglong2 b0 = *(const ulonglong2*)&Bs[k][tx*8];
            ulonglong2 b1 = *(const ulonglong2*)&Bs[k][tx*8+4];
            #pragma unroll
            for (int i = 0; i < 8; i++) {
                unsigned long long ad = f2pack(a[i], a[i]);
                f2fma(acc2[i][0], ad, b0.x);
                f2fma(acc2[i][1], ad, b0.y);
                f2fma(acc2[i][2], ad, b1.x);
                f2fma(acc2[i][3], ad, b1.y);
            }
        }
        __syncthreads();
    }

    #pragma unroll
    for (int i = 0; i < 8; i++) {
        int o = or0 + ty * 8 + i;
        float bi = bias[o];
        float* p = dst + (((size_t)b * CK + o) << 12) + n0 + tx * 8;
        float2 e0 = f2unpack(acc2[i][0]), e1 = f2unpack(acc2[i][1]);
        float2 e2 = f2unpack(acc2[i][2]), e3 = f2unpack(acc2[i][3]);
        float4 v0 = {e0.x+bi, e0.y+bi, e1.x+bi, e1.y+bi};
        float4 v1 = {e2.x+bi, e2.y+bi, e3.x+bi, e3.y+bi};
        *(float4*)p       = v0;
        *(float4*)(p + 4) = v1;
    }
}

// =====================================================================
// Kernel 2: BN training statistics per channel over (B, N) = 32768 vals.
// =====================================================================
__global__ void __launch_bounds__(256) bn_stats_kernel()
{
    const int ck = blockIdx.x;
    float s = 0.f, s2 = 0.f;
    for (int i = threadIdx.x; i < B_ * NPIX; i += 256) {
        int b = i >> 12;
        int n = i & (NPIX - 1);
        float v = g_qk[(((size_t)b * CK + ck) << 12) + n];
        s += v; s2 += v * v;
    }
    #pragma unroll
    for (int off = 16; off > 0; off >>= 1) {
        s  += __shfl_xor_sync(0xffffffffu, s,  off);
        s2 += __shfl_xor_sync(0xffffffffu, s2, off);
    }
    __shared__ float sb[16];
    int w = threadIdx.x >> 5;
    if ((threadIdx.x & 31) == 0) { sb[w] = s; sb[8 + w] = s2; }
    __syncthreads();
    if (threadIdx.x == 0) {
        float S = 0.f, S2 = 0.f;
        #pragma unroll
        for (int i = 0; i < 8; i++) { S += sb[i]; S2 += sb[8 + i]; }
        const float invN = 1.f / (float)(B_ * NPIX);
        float mean = S * invN;
        float var  = S2 * invN - mean * mean;
        g_mean[ck] = mean;
        g_rstd[ck] = rsqrtf(var + EPS);
    }
}

// =====================================================================
// Kernel 3: feat = relu((qk-mean)*rstd*gamma + beta) -> two d_out slots
// =====================================================================
__global__ void __launch_bounds__(256) feat_kernel(
    const float* __restrict__ gamma, const float* __restrict__ beta,
    float* __restrict__ feat1, float* __restrict__ feat2)
{
    int i4 = blockIdx.x * 256 + threadIdx.x;
    int e  = i4 * 4;
    int ck = (e >> 12) & (CK - 1);
    float mu = g_mean[ck], r = g_rstd[ck];
    float sc = r * gamma[ck], be = beta[ck];
    float4 v = *(const float4*)(g_qk + e);
    float4 f;
    f.x = fmaxf(0.f, (v.x - mu) * sc + be);
    f.y = fmaxf(0.f, (v.y - mu) * sc + be);
    f.z = fmaxf(0.f, (v.z - mu) * sc + be);
    f.w = fmaxf(0.f, (v.w - mu) * sc + be);
    *(float4*)(feat1 + e) = f;
    *(float4*)(feat2 + e) = f;
}

// =====================================================================
// Kernel 4: value [B,Cv,N] -> vT [B,N,Cv]  (32x32 smem transpose)
// =====================================================================
__global__ void __launch_bounds__(256) transpose_v_kernel(const float* __restrict__ value)
{
    __shared__ float t[32][33];
    const int b  = blockIdx.z;
    const int n0 = blockIdx.x * 32;
    const int c0 = blockIdx.y * 32;
    #pragma unroll
    for (int r = 0; r < 4; r++) {
        int row = c0 + threadIdx.y + r * 8;
        t[threadIdx.y + r*8][threadIdx.x] =
            value[(((size_t)b * CV + row) << 12) + n0 + threadIdx.x];
    }
    __syncthreads();
    #pragma unroll
    for (int r = 0; r < 4; r++) {
        int row = n0 + threadIdx.y + r * 8;
        g_vT[((size_t)b * NPIX + row) * CV + c0 + threadIdx.x] =
            t[threadIdx.x][threadIdx.y + r*8];
    }
}

// =====================================================================
// Kernel 5: flash attention, fp32 with f32x2 packed FMA inner loops.
//   BM=BN=64, D=256. 256 threads (16x16); each thread: 4x4 of S,
//   4 rows x 16 cols of O (as 8 f32x2 pairs per row).
// =====================================================================
#define PS_LD 65
#define ATTN_SMEM ((16384*3 + 64*PS_LD) * 4)

__global__ void __launch_bounds__(256, 1) attn_kernel(
    const float* __restrict__ feat)   // [B,Ck,N] (d_out feat1 slot)
{
    extern __shared__ __align__(16) float sm[];
    float* Qs = sm;                 // [256][64]  (ck-major, m contiguous)
    float* Ks = sm + 16384;         // [256][64]
    float* Vs = sm + 32768;         // [64][256]  (n-major, cv contiguous)
    float* Ps = sm + 49152;         // [64][PS_LD] transposed: Ps[n][m]

    const int b  = blockIdx.y;
    const int q0 = blockIdx.x * 64;
    const float* f  = feat + (size_t)b * CK * NPIX;
    const float* vt = g_vT + (size_t)b * NPIX * CV;

    const int tid = threadIdx.x;
    const int tx = tid & 15, ty = tid >> 4;
    const int mb = ty * 4, nb = tx * 4;

    // load Q tile once
    #pragma unroll
    for (int r = 0; r < 16; r++) {
        int idx = tid + r * 256;
        int ck = idx >> 4, mq = idx & 15;
        *(float4*)&Qs[ck * 64 + mq * 4] =
            *(const float4*)(f + ((size_t)ck << 12) + q0 + mq * 4);
    }

    float M[4], L[4];
    unsigned long long O2[4][8];
    #pragma unroll
    for (int i = 0; i < 4; i++) {
        M[i] = -1e30f; L[i] = 0.f;
        #pragma unroll
        for (int j = 0; j < 8; j++) O2[i][j] = 0ull;
    }

    for (int kb = 0; kb < NPIX / 64; kb++) {
        const int k0 = kb * 64;
        __syncthreads();   // prior iter finished reading Ks/Vs/Ps
        #pragma unroll
        for (int r = 0; r < 16; r++) {
            int idx = tid + r * 256;
            int ck = idx >> 4, mq = idx & 15;
            *(float4*)&Ks[ck * 64 + mq * 4] =
                *(const float4*)(f + ((size_t)ck << 12) + k0 + mq * 4);
        }
        #pragma unroll
        for (int r = 0; r < 16; r++) {
            int idx = tid + r * 256;
            int n = idx >> 6, cq = idx & 63;
            *(float4*)&Vs[n * 256 + cq * 4] =
                *(const float4*)(vt + (size_t)(k0 + n) * CV + cq * 4);
        }
        __syncthreads();

        // ---- S = Q K^T, f32x2: pairs along n ----
        unsigned long long s2[4][2] = {};
        #pragma unroll 8
        for (int ck = 0; ck < CK; ck++) {
            float4 a = *(float4*)&Qs[ck * 64 + mb];
            ulonglong2 k2 = *(const ulonglong2*)&Ks[ck * 64 + nb];
            unsigned long long a0 = f2pack(a.x, a.x);
            unsigned long long a1 = f2pack(a.y, a.y);
            unsigned long long a2 = f2pack(a.z, a.z);
            unsigned long long a3 = f2pack(a.w, a.w);
            f2fma(s2[0][0], a0, k2.x); f2fma(s2[0][1], a0, k2.y);
            f2fma(s2[1][0], a1, k2.x); f2fma(s2[1][1], a1, k2.y);
            f2fma(s2[2][0], a2, k2.x); f2fma(s2[2][1], a2, k2.y);
            f2fma(s2[3][0], a3, k2.x); f2fma(s2[3][1], a3, k2.y);
        }

        float s[4][4];
        #pragma unroll
        for (int i = 0; i < 4; i++) {
            float2 e0 = f2unpack(s2[i][0]);
            float2 e1 = f2unpack(s2[i][1]);
            s[i][0] = e0.x; s[i][1] = e0.y; s[i][2] = e1.x; s[i][3] = e1.y;
        }

        // ---- online softmax ----
        const float scale = 0.0625f;    // 1/sqrt(256)
        float rm[4];
        #pragma unroll
        for (int i = 0; i < 4; i++) {
            s[i][0] *= scale; s[i][1] *= scale; s[i][2] *= scale; s[i][3] *= scale;
            rm[i] = fmaxf(fmaxf(s[i][0], s[i][1]), fmaxf(s[i][2], s[i][3]));
        }
        #pragma unroll
        for (int off = 8; off > 0; off >>= 1)
            #pragma unroll
            for (int i = 0; i < 4; i++)
                rm[i] = fmaxf(rm[i], __shfl_xor_sync(0xffffffffu, rm[i], off));

        float c[4], rs[4];
        #pragma unroll
        for (int i = 0; i < 4; i++) {
            float mn = fmaxf(M[i], rm[i]);
            c[i] = __expf(M[i] - mn);
            M[i] = mn;
            rs[i] = 0.f;
        }
        #pragma unroll
        for (int i = 0; i < 4; i++)
            #pragma unroll
            for (int j = 0; j < 4; j++) {
                float p = __expf(s[i][j] - M[i]);
                Ps[(nb + j) * PS_LD + mb + i] = p;
                rs[i] += p;
            }
        #pragma unroll
        for (int off = 8; off > 0; off >>= 1)
            #pragma unroll
            for (int i = 0; i < 4; i++)
                rs[i] += __shfl_xor_sync(0xffffffffu, rs[i], off);
        #pragma unroll
        for (int i = 0; i < 4; i++) {
            L[i] = L[i] * c[i] + rs[i];
            unsigned long long cd = f2pack(c[i], c[i]);
            #pragma unroll
            for (int j = 0; j < 8; j++) f2mul(O2[i][j], cd);
        }
        __syncthreads();

        // ---- O += P V  (f32x2: pairs along cv) ----
        #pragma unroll 4
        for (int n = 0; n < 64; n++) {
            unsigned long long p0 = f2pack(Ps[n * PS_LD + mb + 0], Ps[n * PS_LD + mb + 0]);
            unsigned long long p1 = f2pack(Ps[n * PS_LD + mb + 1], Ps[n * PS_LD + mb + 1]);
            unsigned long long p2 = f2pack(Ps[n * PS_LD + mb + 2], Ps[n * PS_LD + mb + 2]);
            unsigned long long p3 = f2pack(Ps[n * PS_LD + mb + 3], Ps[n * PS_LD + mb + 3]);
            #pragma unroll
            for (int j = 0; j < 4; j++) {
                ulonglong2 v2 = *(const ulonglong2*)&Vs[n * 256 + tx * 4 + j * 64];
                f2fma(O2[0][j*2+0], p0, v2.x); f2fma(O2[0][j*2+1], p0, v2.y);
                f2fma(O2[1][j*2+0], p1, v2.x); f2fma(O2[1][j*2+1], p1, v2.y);
                f2fma(O2[2][j*2+0], p2, v2.x); f2fma(O2[2][j*2+1], p2, v2.y);
                f2fma(O2[3][j*2+0], p3, v2.x); f2fma(O2[3][j*2+1], p3, v2.y);
            }
        }
    }

    // ---- write ctx [B,N,Cv] ----
    #pragma unroll
    for (int i = 0; i < 4; i++) {
        float inv = 1.0f / L[i];
        float* dst = g_ctx + ((size_t)b * NPIX + q0 + mb + i) * CV;
        #pragma unroll
        for (int j = 0; j < 4; j++) {
            float2 e0 = f2unpack(O2[i][j*2+0]);
            float2 e1 = f2unpack(O2[i][j*2+1]);
            float4 o4 = {e0.x*inv, e0.y*inv, e1.x*inv, e1.y*inv};
            *(float4*)(dst + tx * 4 + j * 64) = o4;
        }
    }
}

// =====================================================================
// Kernel 6: out[b,co,n] = sum_cv Ww[co,cv]*ctx[b,n,cv] + bw[co]
// =====================================================================
#define B_LD 132
__global__ void __launch_bounds__(256) gemm_out_kernel(
    const float* __restrict__ Ww, const float* __restrict__ bw,
    float* __restrict__ out)
{
    __shared__ __align__(16) float As[G_BK][A_LD];
    __shared__ __align__(16) float Bs[G_BK][B_LD];

    const int b  = blockIdx.z;
    const int o0 = blockIdx.y * G_BM;
    const int n0 = blockIdx.x * G_BN;
    const int tid = threadIdx.x;
    const int tx = tid & 15, ty = tid >> 4;

    unsigned long long acc2[8][4] = {};

    for (int c0 = 0; c0 < CV; c0 += G_BK) {
        #pragma unroll
        for (int r = 0; r < 2; r++) {
            int idx = tid + r * 256;
            int m  = idx >> 2;
            int kq = idx & 3;
            float4 v = *(const float4*)(Ww + (size_t)(o0 + m) * CV + c0 + kq * 4);
            As[kq*4+0][m] = v.x; As[kq*4+1][m] = v.y;
            As[kq*4+2][m] = v.z; As[kq*4+3][m] = v.w;
        }
        #pragma unroll
        for (int r = 0; r < 2; r++) {
            int idx = tid + r * 256;
            int n  = idx >> 2;
            int kq = idx & 3;
            float4 v = *(const float4*)(g_ctx + ((size_t)b * NPIX + n0 + n) * CV + c0 + kq * 4);
            Bs[kq*4+0][n] = v.x; Bs[kq*4+1][n] = v.y;
            Bs[kq*4+2][n] = v.z; Bs[kq*4+3][n] = v.w;
        }
        __syncthreads();
        #pragma unroll
        for (int k = 0; k < G_BK; k++) {
            float a[8];
            *(float4*)&a[0] = *(float4*)&As[k][ty*8];
            *(float4*)&a[4] = *(float4*)&As[k][ty*8+4];
            ulonglong2 b0 = *(const ulonglong2*)&Bs[k][tx*8];
            ulonglong2 b1 = *(const ulonglong2*)&Bs[k][tx*8+4];
            #pragma unroll
            for (int i = 0; i < 8; i++) {
                unsigned long long ad = f2pack(a[i], a[i]);
                f2fma(acc2[i][0], ad, b0.x);
                f2fma(acc2[i][1], ad, b0.y);
                f2fma(acc2[i][2], ad, b1.x);
                f2fma(acc2[i][3], ad, b1.y);
            }
        }
        __syncthreads();
    }

    #pragma unroll
    for (int i = 0; i < 8; i++) {
        int o = o0 + ty * 8 + i;
        float bi = bw[o];
        float* p = out + (((size_t)b * CO + o) << 12) + n0 + tx * 8;
        float2 e0 = f2unpack(acc2[i][0]), e1 = f2unpack(acc2[i][1]);
        float2 e2 = f2unpack(acc2[i][2]), e3 = f2unpack(acc2[i][3]);
        float4 v0 = {e0.x+bi, e0.y+bi, e1.x+bi, e1.y+bi};
        float4 v1 = {e2.x+bi, e2.y+bi, e3.x+bi, e3.y+bi};
        *(float4*)p       = v0;
        *(float4*)(p + 4) = v1;
    }
}

// =====================================================================
// launch
// =====================================================================
extern "C" void kernel_launch(void* const* d_in, const int* in_sizes, int n_in,
                              void* d_out, int out_size)
{
    const float* x     = (const float*)d_in[0];
    const float* Wk    = (const float*)d_in[1];
    const float* bk    = (const float*)d_in[2];
    const float* gamma = (const float*)d_in[3];
    const float* beta  = (const float*)d_in[4];
    const float* Wv    = (const float*)d_in[5];
    const float* bv    = (const float*)d_in[6];
    const float* Ww    = (const float*)d_in[7];
    const float* bw    = (const float*)d_in[8];

    float* out   = (float*)d_out;                        // [8,512,64,64]
    float* feat1 = out   + (size_t)B_ * CO * NPIX;       // [8,256,64,64]
    float* feat2 = feat1 + (size_t)B_ * CK * NPIX;       // [8,256,64,64]
    float* value = feat2 + (size_t)B_ * CK * NPIX;       // [8,256,64,64]

    cudaFuncSetAttribute(attn_kernel,
                         cudaFuncAttributeMaxDynamicSharedMemorySize, ATTN_SMEM);

    // 1) fused QK/V conv1x1 GEMM
    gemm_qkv_kernel<<<dim3(NPIX / G_BN, (CK + CV) / G_BM, B_), 256>>>(
        x, Wk, bk, Wv, bv, value);

    // 2) BN stats
    bn_stats_kernel<<<CK, 256>>>();

    // 3) BN normalize + ReLU -> feat (written twice)
    feat_kernel<<<(B_ * CK * NPIX) / (4 * 256), 256>>>(gamma, beta, feat1, feat2);

    // 4) transpose value -> [B,N,Cv]
    transpose_v_kernel<<<dim3(NPIX / 32, CV / 32, B_), dim3(32, 8)>>>(value);

    // 5) flash attention -> g_ctx [B,N,Cv]
    attn_kernel<<<dim3(NPIX / 64, B_), 256, ATTN_SMEM>>>(feat1);

    // 6) output conv1x1 GEMM
    gemm_out_kernel<<<dim3(NPIX / G_BN, CO / G_BM, B_), 256>>>(Ww, bw, out);
}

// round 15
// speedup vs baseline: 1.0204x; 1.0030x over previous
#include <cuda_runtime.h>
#include <cuda_bf16.h>
#include <cstdint>

// ---------------- problem constants ----------------
#define B_   8
#define C_   512
#define NPIX 4096          // H*W = 64*64
#define CK   256
#define CV   256
#define CO   512
#define EPS  1e-5f

// ---------------- scratch (device globals; no allocation allowed) ----------
__device__ float g_qk [B_ * CK * NPIX];   // conv-k output, pre-BN   [B,Ck,N]
__device__ float g_vT [B_ * NPIX * CV];   // value transposed        [B,N,Cv]
__device__ float g_ctx[B_ * NPIX * CV];   // attention output        [B,N,Cv]
__device__ float g_mean[CK];
__device__ float g_rstd[CK];

// ---------------- packed f32x2 helpers (FFMA2 path, 2x fp32 rate) ----------
__device__ __forceinline__ unsigned long long f2pack(float lo, float hi) {
    unsigned long long r;
    asm("mov.b64 %0, {%1, %2};" : "=l"(r) : "f"(lo), "f"(hi));
    return r;
}
__device__ __forceinline__ void f2fma(unsigned long long& acc,
                                      unsigned long long a, unsigned long long b) {
    asm("fma.rn.f32x2 %0, %1, %2, %0;" : "+l"(acc) : "l"(a), "l"(b));
}
__device__ __forceinline__ void f2mul(unsigned long long& d, unsigned long long a) {
    asm("mul.rn.f32x2 %0, %0, %1;" : "+l"(d) : "l"(a));
}
__device__ __forceinline__ float2 f2unpack(unsigned long long v) {
    float2 f;
    asm("mov.b64 {%0, %1}, %2;" : "=f"(f.x), "=f"(f.y) : "l"(v));
    return f;
}

// =====================================================================
// Kernel 1: fused QKV 1x1 conv GEMM (f32x2 micro-kernel).
// =====================================================================
#define G_BM 128
#define G_BN 128
#define G_BK 16
#define A_LD 132

__global__ void __launch_bounds__(256) gemm_qkv_kernel(
    const float* __restrict__ x,
    const float* __restrict__ Wk, const float* __restrict__ bk,
    const float* __restrict__ Wv, const float* __restrict__ bv,
    float* __restrict__ value)
{
    __shared__ __align__(16) float As[G_BK][A_LD];
    __shared__ __align__(16) float Bs[G_BK][G_BN];

    const int b  = blockIdx.z;
    const int o0 = blockIdx.y * G_BM;
    const int n0 = blockIdx.x * G_BN;
    const int tid = threadIdx.x;
    const int tx = tid & 15, ty = tid >> 4;

    const bool is_k = (o0 < CK);
    const float* W    = is_k ? Wk : Wv;
    const float* bias = is_k ? bk : bv;
    float*       dst  = is_k ? g_qk : value;
    const int or0 = o0 & (CK - 1);

    unsigned long long acc2[8][4] = {};

    for (int c0 = 0; c0 < C_; c0 += G_BK) {
        #pragma unroll
        for (int r = 0; r < 2; r++) {
            int idx = tid + r * 256;
            int m  = idx >> 2;
            int kq = idx & 3;
            float4 v = *(const float4*)(W + (size_t)(or0 + m) * C_ + c0 + kq * 4);
            As[kq*4+0][m] = v.x; As[kq*4+1][m] = v.y;
            As[kq*4+2][m] = v.z; As[kq*4+3][m] = v.w;
        }
        #pragma unroll
        for (int r = 0; r < 2; r++) {
            int idx = tid + r * 256;
            int k  = idx >> 5;
            int nq = idx & 31;
            *(float4*)&Bs[k][nq*4] =
                *(const float4*)(x + (((size_t)b * C_ + c0 + k) << 12) + n0 + nq * 4);
        }
        __syncthreads();
        #pragma unroll
        for (int k = 0; k < G_BK; k++) {
            float a[8];
            *(float4*)&a[0] = *(float4*)&As[k][ty*8];
            *(float4*)&a[4] = *(float4*)&As[k][ty*8+4];
            ulonglong2 b0 = *(const ulonglong2*)&Bs[k][tx*8];
            ulonglong2 b1 = *(const ulonglong2*)&Bs[k][tx*8+4];
            #pragma unroll
            for (int i = 0; i < 8; i++) {
                unsigned long long ad = f2pack(a[i], a[i]);
                f2fma(acc2[i][0], ad, b0.x);
                f2fma(acc2[i][1], ad, b0.y);
                f2fma(acc2[i][2], ad, b1.x);
                f2fma(acc2[i][3], ad, b1.y);
            }
        }
        __syncthreads();
    }

    #pragma unroll
    for (int i = 0; i < 8; i++) {
        int o = or0 + ty * 8 + i;
        float bi = bias[o];
        float* p = dst + (((size_t)b * CK + o) << 12) + n0 + tx * 8;
        float2 e0 = f2unpack(acc2[i][0]), e1 = f2unpack(acc2[i][1]);
        float2 e2 = f2unpack(acc2[i][2]), e3 = f2unpack(acc2[i][3]);
        float4 v0 = {e0.x+bi, e0.y+bi, e1.x+bi, e1.y+bi};
        float4 v1 = {e2.x+bi, e2.y+bi, e3.x+bi, e3.y+bi};
        *(float4*)p       = v0;
        *(float4*)(p + 4) = v1;
    }
}

// =====================================================================
// Kernel 2: BN training statistics per channel over (B, N) = 32768 vals.
// =====================================================================
__global__ void __launch_bounds__(256) bn_stats_kernel()
{
    const int ck = blockIdx.x;
    float s = 0.f, s2 = 0.f;
    for (int i = threadIdx.x; i < B_ * NPIX; i += 256) {
        int b = i >> 12;
        int n = i & (NPIX - 1);
        float v = g_qk[(((size_t)b * CK + ck) << 12) + n];
        s += v; s2 += v * v;
    }
    #pragma unroll
    for (int off = 16; off > 0; off >>= 1) {
        s  += __shfl_xor_sync(0xffffffffu, s,  off);
        s2 += __shfl_xor_sync(0xffffffffu, s2, off);
    }
    __shared__ float sb[16];
    int w = threadIdx.x >> 5;
    if ((threadIdx.x & 31) == 0) { sb[w] = s; sb[8 + w] = s2; }
    __syncthreads();
    if (threadIdx.x == 0) {
        float S = 0.f, S2 = 0.f;
        #pragma unroll
        for (int i = 0; i < 8; i++) { S += sb[i]; S2 += sb[8 + i]; }
        const float invN = 1.f / (float)(B_ * NPIX);
        float mean = S * invN;
        float var  = S2 * invN - mean * mean;
        g_mean[ck] = mean;
        g_rstd[ck] = rsqrtf(var + EPS);
    }
}

// =====================================================================
// Kernel 3: feat = relu((qk-mean)*rstd*gamma + beta) -> two d_out slots
// =====================================================================
__global__ void __launch_bounds__(256) feat_kernel(
    const float* __restrict__ gamma, const float* __restrict__ beta,
    float* __restrict__ feat1, float* __restrict__ feat2)
{
    int i4 = blockIdx.x * 256 + threadIdx.x;
    int e  = i4 * 4;
    int ck = (e >> 12) & (CK - 1);
    float mu = g_mean[ck], r = g_rstd[ck];
    float sc = r * gamma[ck], be = beta[ck];
    float4 v = *(const float4*)(g_qk + e);
    float4 f;
    f.x = fmaxf(0.f, (v.x - mu) * sc + be);
    f.y = fmaxf(0.f, (v.y - mu) * sc + be);
    f.z = fmaxf(0.f, (v.z - mu) * sc + be);
    f.w = fmaxf(0.f, (v.w - mu) * sc + be);
    *(float4*)(feat1 + e) = f;
    *(float4*)(feat2 + e) = f;
}

// =====================================================================
// Kernel 4: value [B,Cv,N] -> vT [B,N,Cv]  (32x32 smem transpose)
// =====================================================================
__global__ void __launch_bounds__(256) transpose_v_kernel(const float* __restrict__ value)
{
    __shared__ float t[32][33];
    const int b  = blockIdx.z;
    const int n0 = blockIdx.x * 32;
    const int c0 = blockIdx.y * 32;
    #pragma unroll
    for (int r = 0; r < 4; r++) {
        int row = c0 + threadIdx.y + r * 8;
        t[threadIdx.y + r*8][threadIdx.x] =
            value[(((size_t)b * CV + row) << 12) + n0 + threadIdx.x];
    }
    __syncthreads();
    #pragma unroll
    for (int r = 0; r < 4; r++) {
        int row = n0 + threadIdx.y + r * 8;
        g_vT[((size_t)b * NPIX + row) * CV + c0 + threadIdx.x] =
            t[threadIdx.x][threadIdx.y + r*8];
    }
}

// =====================================================================
// Kernel 5: flash attention, fp32 with f32x2 packed FMA inner loops.
//   BM=BN=64, D=256. 256 threads (16x16); each thread: 4x4 of S,
//   4 rows x 16 cols of O (as 8 f32x2 pairs per row).
// =====================================================================
#define PS_LD 65
#define ATTN_SMEM ((16384*3 + 64*PS_LD) * 4)

__global__ void __launch_bounds__(256, 1) attn_kernel(
    const float* __restrict__ feat)   // [B,Ck,N] (d_out feat1 slot)
{
    extern __shared__ __align__(16) float sm[];
    float* Qs = sm;                 // [256][64]  (ck-major, m contiguous)
    float* Ks = sm + 16384;         // [256][64]
    float* Vs = sm + 32768;         // [64][256]  (n-major, cv contiguous)
    float* Ps = sm + 49152;         // [64][PS_LD] transposed: Ps[n][m]

    const int b  = blockIdx.y;
    const int q0 = blockIdx.x * 64;
    const float* f  = feat + (size_t)b * CK * NPIX;
    const float* vt = g_vT + (size_t)b * NPIX * CV;

    const int tid = threadIdx.x;
    const int tx = tid & 15, ty = tid >> 4;
    const int mb = ty * 4, nb = tx * 4;

    // load Q tile once
    #pragma unroll
    for (int r = 0; r < 16; r++) {
        int idx = tid + r * 256;
        int ck = idx >> 4, mq = idx & 15;
        *(float4*)&Qs[ck * 64 + mq * 4] =
            *(const float4*)(f + ((size_t)ck << 12) + q0 + mq * 4);
    }

    float M[4], L[4];
    unsigned long long O2[4][8];
    #pragma unroll
    for (int i = 0; i < 4; i++) {
        M[i] = -1e30f; L[i] = 0.f;
        #pragma unroll
        for (int j = 0; j < 8; j++) O2[i][j] = 0ull;
    }

    for (int kb = 0; kb < NPIX / 64; kb++) {
        const int k0 = kb * 64;
        __syncthreads();   // prior iter finished reading Ks/Vs/Ps
        #pragma unroll
        for (int r = 0; r < 16; r++) {
            int idx = tid + r * 256;
            int ck = idx >> 4, mq = idx & 15;
            *(float4*)&Ks[ck * 64 + mq * 4] =
                *(const float4*)(f + ((size_t)ck << 12) + k0 + mq * 4);
        }
        #pragma unroll
        for (int r = 0; r < 16; r++) {
            int idx = tid + r * 256;
            int n = idx >> 6, cq = idx & 63;
            *(float4*)&Vs[n * 256 + cq * 4] =
                *(const float4*)(vt + (size_t)(k0 + n) * CV + cq * 4);
        }
        __syncthreads();

        // ---- S = Q K^T, f32x2: pairs along n ----
        unsigned long long s2[4][2] = {};
        #pragma unroll 8
        for (int ck = 0; ck < CK; ck++) {
            float4 a = *(float4*)&Qs[ck * 64 + mb];
            ulonglong2 k2 = *(const ulonglong2*)&Ks[ck * 64 + nb];
            unsigned long long a0 = f2pack(a.x, a.x);
            unsigned long long a1 = f2pack(a.y, a.y);
            unsigned long long a2 = f2pack(a.z, a.z);
            unsigned long long a3 = f2pack(a.w, a.w);
            f2fma(s2[0][0], a0, k2.x); f2fma(s2[0][1], a0, k2.y);
            f2fma(s2[1][0], a1, k2.x); f2fma(s2[1][1], a1, k2.y);
            f2fma(s2[2][0], a2, k2.x); f2fma(s2[2][1], a2, k2.y);
            f2fma(s2[3][0], a3, k2.x); f2fma(s2[3][1], a3, k2.y);
        }

        float s[4][4];
        #pragma unroll
        for (int i = 0; i < 4; i++) {
            float2 e0 = f2unpack(s2[i][0]);
            float2 e1 = f2unpack(s2[i][1]);
            s[i][0] = e0.x; s[i][1] = e0.y; s[i][2] = e1.x; s[i][3] = e1.y;
        }

        // ---- online softmax ----
        const float scale = 0.0625f;    // 1/sqrt(256)
        float rm[4];
        #pragma unroll
        for (int i = 0; i < 4; i++) {
            s[i][0] *= scale; s[i][1] *= scale; s[i][2] *= scale; s[i][3] *= scale;
            rm[i] = fmaxf(fmaxf(s[i][0], s[i][1]), fmaxf(s[i][2], s[i][3]));
        }
        #pragma unroll
        for (int off = 8; off > 0; off >>= 1)
            #pragma unroll
            for (int i = 0; i < 4; i++)
                rm[i] = fmaxf(rm[i], __shfl_xor_sync(0xffffffffu, rm[i], off));

        float c[4], rs[4];
        #pragma unroll
        for (int i = 0; i < 4; i++) {
            float mn = fmaxf(M[i], rm[i]);
            c[i] = __expf(M[i] - mn);
            M[i] = mn;
            rs[i] = 0.f;
        }
        #pragma unroll
        for (int i = 0; i < 4; i++)
            #pragma unroll
            for (int j = 0; j < 4; j++) {
                float p = __expf(s[i][j] - M[i]);
                Ps[(nb + j) * PS_LD + mb + i] = p;
                rs[i] += p;
            }
        #pragma unroll
        for (int off = 8; off > 0; off >>= 1)
            #pragma unroll
            for (int i = 0; i < 4; i++)
                rs[i] += __shfl_xor_sync(0xffffffffu, rs[i], off);
        #pragma unroll
        for (int i = 0; i < 4; i++) {
            L[i] = L[i] * c[i] + rs[i];
            unsigned long long cd = f2pack(c[i], c[i]);
            #pragma unroll
            for (int j = 0; j < 8; j++) f2mul(O2[i][j], cd);
        }
        __syncthreads();

        // ---- O += P V  (f32x2: pairs along cv) ----
        #pragma unroll 4
        for (int n = 0; n < 64; n++) {
            unsigned long long p0 = f2pack(Ps[n * PS_LD + mb + 0], Ps[n * PS_LD + mb + 0]);
            unsigned long long p1 = f2pack(Ps[n * PS_LD + mb + 1], Ps[n * PS_LD + mb + 1]);
            unsigned long long p2 = f2pack(Ps[n * PS_LD + mb + 2], Ps[n * PS_LD + mb + 2]);
            unsigned long long p3 = f2pack(Ps[n * PS_LD + mb + 3], Ps[n * PS_LD + mb + 3]);
            #pragma unroll
            for (int j = 0; j < 4; j++) {
                ulonglong2 v2 = *(const ulonglong2*)&Vs[n * 256 + tx * 4 + j * 64];
                f2fma(O2[0][j*2+0], p0, v2.x); f2fma(O2[0][j*2+1], p0, v2.y);
                f2fma(O2[1][j*2+0], p1, v2.x); f2fma(O2[1][j*2+1], p1, v2.y);
                f2fma(O2[2][j*2+0], p2, v2.x); f2fma(O2[2][j*2+1], p2, v2.y);
                f2fma(O2[3][j*2+0], p3, v2.x); f2fma(O2[3][j*2+1], p3, v2.y);
            }
        }
    }

    // ---- write ctx [B,N,Cv] ----
    #pragma unroll
    for (int i = 0; i < 4; i++) {
        float inv = 1.0f / L[i];
        float* dst = g_ctx + ((size_t)b * NPIX + q0 + mb + i) * CV;
        #pragma unroll
        for (int j = 0; j < 4; j++) {
            float2 e0 = f2unpack(O2[i][j*2+0]);
            float2 e1 = f2unpack(O2[i][j*2+1]);
            float4 o4 = {e0.x*inv, e0.y*inv, e1.x*inv, e1.y*inv};
            *(float4*)(dst + tx * 4 + j * 64) = o4;
        }
    }
}

// =====================================================================
// Kernel 6: out[b,co,n] = sum_cv Ww[co,cv]*ctx[b,n,cv] + bw[co]
// =====================================================================
#define B_LD 132
__global__ void __launch_bounds__(256) gemm_out_kernel(
    const float* __restrict__ Ww, const float* __restrict__ bw,
    float* __restrict__ out)
{
    __shared__ __align__(16) float As[G_BK][A_LD];
    __shared__ __align__(16) float Bs[G_BK][B_LD];

    const int b  = blockIdx.z;
    const int o0 = blockIdx.y * G_BM;
    const int n0 = blockIdx.x * G_BN;
    const int tid = threadIdx.x;
    const int tx = tid & 15, ty = tid >> 4;

    unsigned long long acc2[8][4] = {};

    for (int c0 = 0; c0 < CV; c0 += G_BK) {
        #pragma unroll
        for (int r = 0; r < 2; r++) {
            int idx = tid + r * 256;
            int m  = idx >> 2;
            int kq = idx & 3;
            float4 v = *(const float4*)(Ww + (size_t)(o0 + m) * CV + c0 + kq * 4);
            As[kq*4+0][m] = v.x; As[kq*4+1][m] = v.y;
            As[kq*4+2][m] = v.z; As[kq*4+3][m] = v.w;
        }
        #pragma unroll
        for (int r = 0; r < 2; r++) {
            int idx = tid + r * 256;
            int n  = idx >> 2;
            int kq = idx & 3;
            float4 v = *(const float4*)(g_ctx + ((size_t)b * NPIX + n0 + n) * CV + c0 + kq * 4);
            Bs[kq*4+0][n] = v.x; Bs[kq*4+1][n] = v.y;
            Bs[kq*4+2][n] = v.z; Bs[kq*4+3][n] = v.w;
        }
        __syncthreads();
        #pragma unroll
        for (int k = 0; k < G_BK; k++) {
            float a[8];
            *(float4*)&a[0] = *(float4*)&As[k][ty*8];
            *(float4*)&a[4] = *(float4*)&As[k][ty*8+4];
            ulonglong2 b0 = *(const ulonglong2*)&Bs[k][tx*8];
            ulonglong2 b1 = *(const ulonglong2*)&Bs[k][tx*8+4];
            #pragma unroll
            for (int i = 0; i < 8; i++) {
                unsigned long long ad = f2pack(a[i], a[i]);
                f2fma(acc2[i][0], ad, b0.x);
                f2fma(acc2[i][1], ad, b0.y);
                f2fma(acc2[i][2], ad, b1.x);
                f2fma(acc2[i][3], ad, b1.y);
            }
        }
        __syncthreads();
    }

    #pragma unroll
    for (int i = 0; i < 8; i++) {
        int o = o0 + ty * 8 + i;
        float bi = bw[o];
        float* p = out + (((size_t)b * CO + o) << 12) + n0 + tx * 8;
        float2 e0 = f2unpack(acc2[i][0]), e1 = f2unpack(acc2[i][1]);
        float2 e2 = f2unpack(acc2[i][2]), e3 = f2unpack(acc2[i][3]);
        float4 v0 = {e0.x+bi, e0.y+bi, e1.x+bi, e1.y+bi};
        float4 v1 = {e2.x+bi, e2.y+bi, e3.x+bi, e3.y+bi};
        *(float4*)p       = v0;
        *(float4*)(p + 4) = v1;
    }
}

// =====================================================================
// launch
// =====================================================================
extern "C" void kernel_launch(void* const* d_in, const int* in_sizes, int n_in,
                              void* d_out, int out_size)
{
    const float* x     = (const float*)d_in[0];
    const float* Wk    = (const float*)d_in[1];
    const float* bk    = (const float*)d_in[2];
    const float* gamma = (const float*)d_in[3];
    const float* beta  = (const float*)d_in[4];
    const float* Wv    = (const float*)d_in[5];
    const float* bv    = (const float*)d_in[6];
    const float* Ww    = (const float*)d_in[7];
    const float* bw    = (const float*)d_in[8];

    float* out   = (float*)d_out;                        // [8,512,64,64]
    float* feat1 = out   + (size_t)B_ * CO * NPIX;       // [8,256,64,64]
    float* feat2 = feat1 + (size_t)B_ * CK * NPIX;       // [8,256,64,64]
    float* value = feat2 + (size_t)B_ * CK * NPIX;       // [8,256,64,64]

    cudaFuncSetAttribute(attn_kernel,
                         cudaFuncAttributeMaxDynamicSharedMemorySize, ATTN_SMEM);

    // 1) fused QK/V conv1x1 GEMM
    gemm_qkv_kernel<<<dim3(NPIX / G_BN, (CK + CV) / G_BM, B_), 256>>>(
        x, Wk, bk, Wv, bv, value);

    // 2) BN stats
    bn_stats_kernel<<<CK, 256>>>();

    // 3) BN normalize + ReLU -> feat (written twice)
    feat_kernel<<<(B_ * CK * NPIX) / (4 * 256), 256>>>(gamma, beta, feat1, feat2);

    // 4) transpose value -> [B,N,Cv]
    transpose_v_kernel<<<dim3(NPIX / 32, CV / 32, B_), dim3(32, 8)>>>(value);

    // 5) flash attention -> g_ctx [B,N,Cv]
    attn_kernel<<<dim3(NPIX / 64, B_), 256, ATTN_SMEM>>>(feat1);

    // 6) output conv1x1 GEMM
    gemm_out_kernel<<<dim3(NPIX / G_BN, CO / G_BM, B_), 256>>>(Ww, bw, out);
}